// round 6
// baseline (speedup 1.0000x reference)
#include <cuda_runtime.h>
#include <cuda_fp16.h>
#include <cstdint>

static constexpr int BATCH = 65536;
static constexpr int KD    = 512;
static constexpr int ND    = 512;

static constexpr int BM = 64;
static constexpr int BN = 256;
static constexpr int BK = 32;           // 32 fp16 = 64B B-rows
static constexpr int NKITER = KD / BK;  // 16
static constexpr int STAGES = 3;

static constexpr int A_BYTES     = BM * KD * 2;          // 65536 (resident, 1024B rows)
static constexpr int B_STAGE     = BN * BK * 2;          // 16384 (64B rows)
static constexpr int SMEM_TOTAL  = A_BYTES + STAGES * B_STAGE;  // 114688

// ---------------- fp16 W scratch, blocked [kt][n][32] (no allocs allowed) ----------------
__device__ __align__(256) __half g_wb[ND * KD];

// ---------------- helpers ----------------
static __device__ __forceinline__ uint32_t smem_u32(const void* p) {
    uint32_t a;
    asm("{ .reg .u64 t; cvta.to.shared.u64 t, %1; cvt.u32.u64 %0, t; }"
        : "=r"(a) : "l"(p));
    return a;
}

__device__ __forceinline__ void cp16(uint32_t dst, const void* src) {
    asm volatile("cp.async.cg.shared.global [%0], [%1], 16;"
                 :: "r"(dst), "l"(src) : "memory");
}
__device__ __forceinline__ void cp_commit() {
    asm volatile("cp.async.commit_group;" ::: "memory");
}
template <int N>
__device__ __forceinline__ void cp_wait() {
    asm volatile("cp.async.wait_group %0;" :: "n"(N) : "memory");
}

__device__ __forceinline__ void ldsm4(uint32_t& r0, uint32_t& r1, uint32_t& r2,
                                      uint32_t& r3, uint32_t addr) {
    asm volatile("ldmatrix.sync.aligned.m8n8.x4.shared.b16 {%0,%1,%2,%3}, [%4];"
                 : "=r"(r0), "=r"(r1), "=r"(r2), "=r"(r3) : "r"(addr));
}

__device__ __forceinline__ void mma16816(float* d, const uint32_t* a, const uint32_t* b) {
    asm volatile(
        "mma.sync.aligned.m16n8k16.row.col.f32.f16.f16.f32 "
        "{%0,%1,%2,%3}, {%4,%5,%6,%7}, {%8,%9}, {%0,%1,%2,%3};"
        : "+f"(d[0]), "+f"(d[1]), "+f"(d[2]), "+f"(d[3])
        : "r"(a[0]), "r"(a[1]), "r"(a[2]), "r"(a[3]), "r"(b[0]), "r"(b[1]));
}

// ---------------- W prepass: fp32 row-major -> fp16 blocked [kt][n][32] ----------------
__global__ void __launch_bounds__(256) cvt_w_kernel(const float* __restrict__ s) {
    size_t idx = (size_t)blockIdx.x * 256 + threadIdx.x;   // one float4 each
    int n  = (int)(idx >> 7);          // row (out-feature)
    int c4 = (int)(idx & 127);         // float4 within row
    float4 v = reinterpret_cast<const float4*>(s)[idx];
    __half2 h0 = __floats2half2_rn(v.x, v.y);
    __half2 h1 = __floats2half2_rn(v.z, v.w);
    uint2 u;
    u.x = *reinterpret_cast<uint32_t*>(&h0);
    u.y = *reinterpret_cast<uint32_t*>(&h1);
    int kt = c4 >> 3;                  // which K-block of 32
    int ci = c4 & 7;                   // float4 within K-block (8 per block)
    size_t off = (size_t)kt * (ND * BK) + (size_t)n * BK + ci * 4;
    *reinterpret_cast<uint2*>(g_wb + off) = u;
}

// ---------------- fused GEMM ----------------
// A smem: 64 rows x 1024B; elem chunk c (16B units, 0..63) at
//   r*1024 + 16*((c & ~7) + ((c&7) ^ (r&7)))
// B stage: 256 rows x 64B; chunk c (0..3) at r*64 + 16*(c ^ ((r>>1)&3))
__global__ void __launch_bounds__(256, 2)
gemm_fused_kernel(const float* __restrict__ X, const float* __restrict__ Bv,
                  float* __restrict__ Y) {
    extern __shared__ __align__(1024) char smem[];
    const uint32_t sa = smem_u32(smem);               // A resident
    const uint32_t sbb = sa + A_BYTES;                // B stages

    const int tid  = threadIdx.x;
    const int wid  = tid >> 5;
    const int lane = tid & 31;

    const int bm = blockIdx.x >> 1;
    const int bn = blockIdx.x & 1;
    const int row0 = bm * BM;
    const int col0 = bn * BN;

    // ---- B staging geometry: idx = tid + i*256 over 1024 chunks ----
    auto stageB = [&](int kt, int slot) {
        const uint32_t base = sbb + slot * B_STAGE;
        const __half* src = g_wb + (size_t)kt * (ND * BK) + (size_t)col0 * BK;
#pragma unroll
        for (int i = 0; i < 4; i++) {
            int idx = tid + i * 256;
            int r = idx >> 2, c = idx & 3;
            uint32_t dst = base + (uint32_t)(r * 64 + ((c ^ ((r >> 1) & 3)) << 4));
            cp16(dst, src + (size_t)r * BK + c * 8);
        }
    };

    stageB(0, 0); cp_commit();
    stageB(1, 1); cp_commit();

    // ---- A prologue: convert x fp32 -> fp16 resident tile ----
    {
        const float* xs = X + (size_t)row0 * KD;
#pragma unroll
        for (int i = 0; i < 16; i++) {
            int idx = tid + i * 256;          // 4096 16B-chunks
            int r = idx >> 6, c = idx & 63;   // row, 16B chunk (8 fp16 = 8 fp32 src)
            const float4* sp = reinterpret_cast<const float4*>(xs + (size_t)r * KD + c * 8);
            float4 v0 = sp[0], v1 = sp[1];
            __half2 h0 = __floats2half2_rn(v0.x, v0.y);
            __half2 h1 = __floats2half2_rn(v0.z, v0.w);
            __half2 h2 = __floats2half2_rn(v1.x, v1.y);
            __half2 h3 = __floats2half2_rn(v1.z, v1.w);
            uint4 u;
            u.x = *reinterpret_cast<uint32_t*>(&h0);
            u.y = *reinterpret_cast<uint32_t*>(&h1);
            u.z = *reinterpret_cast<uint32_t*>(&h2);
            u.w = *reinterpret_cast<uint32_t*>(&h3);
            uint32_t dst = sa + (uint32_t)(r * 1024 + (((c & ~7) + ((c & 7) ^ (r & 7))) << 4));
            *reinterpret_cast<uint4*>(smem + (dst - sa)) = u;
        }
    }
    __syncthreads();   // A ready for all warps

    // ---- fragment addressing ----
    const int wm = wid & 1;          // M offset 0/32
    const int wn = wid >> 1;         // N offset 0..3 * 64
    const int lr  = lane & 15;
    const int lc  = lane >> 4;       // 0/1 -> +16B k chunk
    const int sw7 = lane & 7;        // A xor term (row&7)
    const int bsw = (lr >> 1) & 3;   // B xor term ((row>>1)&3)

    uint32_t aRow[2], bRow[4];
#pragma unroll
    for (int mt = 0; mt < 2; mt++)
        aRow[mt] = sa + (uint32_t)((wm * 32 + mt * 16 + lr) * 1024);
#pragma unroll
    for (int nb = 0; nb < 4; nb++)
        bRow[nb] = (uint32_t)((wn * 64 + nb * 16 + lr) * 64);

    float acc[2][8][4];
#pragma unroll
    for (int i = 0; i < 2; i++)
#pragma unroll
        for (int j = 0; j < 8; j++)
#pragma unroll
            for (int e = 0; e < 4; e++) acc[i][j][e] = 0.0f;

    for (int kt = 0; kt < NKITER; kt++) {
        cp_wait<1>();
        __syncthreads();
        if (kt + 2 < NKITER) stageB(kt + 2, (kt + 2) % STAGES);
        cp_commit();

        const uint32_t bbase = sbb + (kt % STAGES) * B_STAGE;
#pragma unroll
        for (int ks = 0; ks < 2; ks++) {
            // A chunk index (16B units within 1024B row)
            const uint32_t ca = (uint32_t)(kt * 4 + ks * 2 + lc);
            const uint32_t aoff = ((ca & ~7u) + ((ca & 7u) ^ (uint32_t)sw7)) << 4;
            // B chunk index (0..3)
            const uint32_t cb = (uint32_t)(ks * 2 + lc);
            const uint32_t boff = ((cb ^ (uint32_t)bsw) & 3u) << 4;

            uint32_t af[2][4], bf[4][4];
#pragma unroll
            for (int mt = 0; mt < 2; mt++)
                ldsm4(af[mt][0], af[mt][1], af[mt][2], af[mt][3], aRow[mt] + aoff);
#pragma unroll
            for (int nb = 0; nb < 4; nb++)
                ldsm4(bf[nb][0], bf[nb][1], bf[nb][2], bf[nb][3], bbase + bRow[nb] + boff);
#pragma unroll
            for (int mt = 0; mt < 2; mt++) {
#pragma unroll
                for (int nt = 0; nt < 8; nt++) {
                    uint32_t bb[2] = { bf[nt >> 1][(nt & 1)],
                                       bf[nt >> 1][(nt & 1) + 2] };
                    mma16816(acc[mt][nt], af[mt], bb);
                }
            }
        }
    }

    // ---- epilogue: bias + fp32 store (warp covers 32 rows x 64 cols) ----
    const int crow = row0 + wm * 32;
    const int ccol = col0 + wn * 64;
#pragma unroll
    for (int nt = 0; nt < 8; nt++) {
        const int c = ccol + nt * 8 + (lane & 3) * 2;
        const float2 bv = *reinterpret_cast<const float2*>(Bv + c);
#pragma unroll
        for (int mt = 0; mt < 2; mt++) {
            const int r = crow + mt * 16 + (lane >> 2);
            float2 v0, v1;
            v0.x = acc[mt][nt][0] + bv.x;
            v0.y = acc[mt][nt][1] + bv.y;
            v1.x = acc[mt][nt][2] + bv.x;
            v1.y = acc[mt][nt][3] + bv.y;
            *reinterpret_cast<float2*>(Y + (size_t)r * ND + c) = v0;
            *reinterpret_cast<float2*>(Y + (size_t)(r + 8) * ND + c) = v1;
        }
    }
}

extern "C" void kernel_launch(void* const* d_in, const int* in_sizes, int n_in,
                              void* d_out, int out_size) {
    const float* x = nullptr;
    const float* w = nullptr;
    const float* b = nullptr;
    for (int i = 0; i < n_in; i++) {
        if (in_sizes[i] == BATCH * KD)   x = (const float*)d_in[i];
        else if (in_sizes[i] == ND * KD) w = (const float*)d_in[i];
        else if (in_sizes[i] == ND)      b = (const float*)d_in[i];
    }
    float* out = (float*)d_out;

    cvt_w_kernel<<<(ND * KD / 4) / 256, 256>>>(w);   // 256 blocks, ~1 us

    cudaFuncSetAttribute(gemm_fused_kernel,
                         cudaFuncAttributeMaxDynamicSharedMemorySize, SMEM_TOTAL);
    gemm_fused_kernel<<<(BATCH / BM) * (ND / BN), 256, SMEM_TOTAL>>>(x, b, out);
}

// round 7
// speedup vs baseline: 1.0102x; 1.0102x over previous
#include <cuda_runtime.h>
#include <cuda_fp16.h>
#include <cstdint>

static constexpr int BATCH = 65536;
static constexpr int KD    = 512;
static constexpr int ND    = 512;

static constexpr int BM = 64;
static constexpr int BN = 256;
static constexpr int BK = 32;           // 32 fp16 = 64B B-rows
static constexpr int NKITER = KD / BK;  // 16
static constexpr int STAGES = 3;

static constexpr int A_BYTES     = BM * KD * 2;                 // 65536 (resident)
static constexpr int B_STAGE     = BN * BK * 2;                 // 16384
static constexpr int SMEM_TOTAL  = A_BYTES + STAGES * B_STAGE;  // 114688

// ---------------- fp16 W scratch, blocked [kt][n][32] (no allocs allowed) ----------------
__device__ __align__(256) __half g_wb[ND * KD];

// ---------------- helpers ----------------
static __device__ __forceinline__ uint32_t smem_u32(const void* p) {
    uint32_t a;
    asm("{ .reg .u64 t; cvta.to.shared.u64 t, %1; cvt.u32.u64 %0, t; }"
        : "=r"(a) : "l"(p));
    return a;
}

__device__ __forceinline__ void cp16(uint32_t dst, const void* src) {
    asm volatile("cp.async.cg.shared.global [%0], [%1], 16;"
                 :: "r"(dst), "l"(src) : "memory");
}
__device__ __forceinline__ void cp_commit() {
    asm volatile("cp.async.commit_group;" ::: "memory");
}
template <int N>
__device__ __forceinline__ void cp_wait() {
    asm volatile("cp.async.wait_group %0;" :: "n"(N) : "memory");
}

__device__ __forceinline__ void ldsm4(uint32_t& r0, uint32_t& r1, uint32_t& r2,
                                      uint32_t& r3, uint32_t addr) {
    asm volatile("ldmatrix.sync.aligned.m8n8.x4.shared.b16 {%0,%1,%2,%3}, [%4];"
                 : "=r"(r0), "=r"(r1), "=r"(r2), "=r"(r3) : "r"(addr));
}

__device__ __forceinline__ void mma16816(float* d, const uint32_t* a, const uint32_t* b) {
    asm volatile(
        "mma.sync.aligned.m16n8k16.row.col.f32.f16.f16.f32 "
        "{%0,%1,%2,%3}, {%4,%5,%6,%7}, {%8,%9}, {%0,%1,%2,%3};"
        : "+f"(d[0]), "+f"(d[1]), "+f"(d[2]), "+f"(d[3])
        : "r"(a[0]), "r"(a[1]), "r"(a[2]), "r"(a[3]), "r"(b[0]), "r"(b[1]));
}

// ---------------- W prepass: fp32 row-major -> fp16 blocked [kt][n][32] ----------------
__global__ void __launch_bounds__(256) cvt_w_kernel(const float* __restrict__ s) {
    size_t idx = (size_t)blockIdx.x * 256 + threadIdx.x;   // one float4 each
    int n  = (int)(idx >> 7);          // out-feature row
    int c4 = (int)(idx & 127);         // float4 within row
    float4 v = reinterpret_cast<const float4*>(s)[idx];
    __half2 h0 = __floats2half2_rn(v.x, v.y);
    __half2 h1 = __floats2half2_rn(v.z, v.w);
    uint2 u;
    u.x = *reinterpret_cast<uint32_t*>(&h0);
    u.y = *reinterpret_cast<uint32_t*>(&h1);
    int kt = c4 >> 3;
    int ci = c4 & 7;
    size_t off = (size_t)kt * (ND * BK) + (size_t)n * BK + ci * 4;
    *reinterpret_cast<uint2*>(g_wb + off) = u;
}

// ---------------- fused GEMM: 128 threads, warp tile 64x64 ----------------
// A smem: 64 rows x 1024B; 16B chunk c (0..63) of row r at
//   r*1024 + 16*((c & ~7) + ((c&7) ^ (r&7)))
// B stage: 256 rows x 64B; chunk c (0..3) of row r at r*64 + 16*(c ^ ((r>>1)&3))
__global__ void __launch_bounds__(128, 2)
gemm_fused_kernel(const float* __restrict__ X, const float* __restrict__ Bv,
                  float* __restrict__ Y) {
    extern __shared__ __align__(1024) char smem[];
    const uint32_t sa  = smem_u32(smem);      // A resident
    const uint32_t sbb = sa + A_BYTES;        // B stages

    const int tid  = threadIdx.x;
    const int wid  = tid >> 5;                // 0..3 -> N offset wid*64
    const int lane = tid & 31;

    const int bm = blockIdx.x >> 1;
    const int bn = blockIdx.x & 1;
    const int row0 = bm * BM;
    const int col0 = bn * BN;

    // ---- B staging: 1024 chunks, 128 threads x 8 ----
    auto stageB = [&](int kt, int slot) {
        const uint32_t base = sbb + slot * B_STAGE;
        const __half* src = g_wb + (size_t)kt * (ND * BK) + (size_t)col0 * BK;
#pragma unroll
        for (int i = 0; i < 8; i++) {
            int idx = tid + i * 128;
            int r = idx >> 2, c = idx & 3;
            uint32_t dst = base + (uint32_t)(r * 64 + ((c ^ ((r >> 1) & 3)) << 4));
            cp16(dst, src + (size_t)r * BK + c * 8);
        }
    };

    stageB(0, 0); cp_commit();
    stageB(1, 1); cp_commit();

    // ---- A prologue: convert x fp32 -> fp16 resident tile (4096 chunks / 128 thr) ----
    {
        const float* xs = X + (size_t)row0 * KD;
#pragma unroll 8
        for (int i = 0; i < 32; i++) {
            int idx = tid + i * 128;
            int r = idx >> 6, c = idx & 63;
            const float4* sp = reinterpret_cast<const float4*>(xs + (size_t)r * KD + c * 8);
            float4 v0 = sp[0], v1 = sp[1];
            __half2 h0 = __floats2half2_rn(v0.x, v0.y);
            __half2 h1 = __floats2half2_rn(v0.z, v0.w);
            __half2 h2 = __floats2half2_rn(v1.x, v1.y);
            __half2 h3 = __floats2half2_rn(v1.z, v1.w);
            uint4 u;
            u.x = *reinterpret_cast<uint32_t*>(&h0);
            u.y = *reinterpret_cast<uint32_t*>(&h1);
            u.z = *reinterpret_cast<uint32_t*>(&h2);
            u.w = *reinterpret_cast<uint32_t*>(&h3);
            uint32_t off = (uint32_t)(r * 1024 + (((c & ~7) + ((c & 7) ^ (r & 7))) << 4));
            *reinterpret_cast<uint4*>(smem + off) = u;
        }
    }
    __syncthreads();

    // ---- fragment addressing ----
    const int lr  = lane & 15;
    const int lc  = lane >> 4;        // 0/1 -> +16B k-chunk
    const int sw7 = lane & 7;         // A xor term
    const int bsw = (lr >> 1) & 3;    // B xor term

    uint32_t aRow[4], bRow[4];
#pragma unroll
    for (int mt = 0; mt < 4; mt++)
        aRow[mt] = sa + (uint32_t)((mt * 16 + lr) * 1024);
#pragma unroll
    for (int nb = 0; nb < 4; nb++)
        bRow[nb] = (uint32_t)((wid * 64 + nb * 16 + lr) * 64);

    float acc[4][8][4];
#pragma unroll
    for (int i = 0; i < 4; i++)
#pragma unroll
        for (int j = 0; j < 8; j++)
#pragma unroll
            for (int e = 0; e < 4; e++) acc[i][j][e] = 0.0f;

    for (int kt = 0; kt < NKITER; kt++) {
        cp_wait<1>();
        __syncthreads();
        if (kt + 2 < NKITER) stageB(kt + 2, (kt + 2) % STAGES);
        cp_commit();

        const uint32_t bbase = sbb + (kt % STAGES) * B_STAGE;

        // load ALL fragments for both ks steps, then drain MMAs (ptxas overlaps)
        uint32_t af[2][4][4], bf[2][4][4];
#pragma unroll
        for (int ks = 0; ks < 2; ks++) {
            const uint32_t ca = (uint32_t)(kt * 4 + ks * 2 + lc);
            const uint32_t aoff = ((ca & ~7u) + ((ca & 7u) ^ (uint32_t)sw7)) << 4;
            const uint32_t cb = (uint32_t)(ks * 2 + lc);
            const uint32_t boff = ((cb ^ (uint32_t)bsw) & 3u) << 4;
#pragma unroll
            for (int mt = 0; mt < 4; mt++)
                ldsm4(af[ks][mt][0], af[ks][mt][1], af[ks][mt][2], af[ks][mt][3],
                      aRow[mt] + aoff);
#pragma unroll
            for (int nb = 0; nb < 4; nb++)
                ldsm4(bf[ks][nb][0], bf[ks][nb][1], bf[ks][nb][2], bf[ks][nb][3],
                      bbase + bRow[nb] + boff);
        }
#pragma unroll
        for (int ks = 0; ks < 2; ks++) {
#pragma unroll
            for (int mt = 0; mt < 4; mt++) {
#pragma unroll
                for (int nt = 0; nt < 8; nt++) {
                    uint32_t bb[2] = { bf[ks][nt >> 1][(nt & 1)],
                                       bf[ks][nt >> 1][(nt & 1) + 2] };
                    mma16816(acc[mt][nt], af[ks][mt], bb);
                }
            }
        }
    }

    // ---- epilogue: bias + fp32 store (warp covers 64 rows x 64 cols) ----
    const int ccol = col0 + wid * 64;
#pragma unroll
    for (int nt = 0; nt < 8; nt++) {
        const int c = ccol + nt * 8 + (lane & 3) * 2;
        const float2 bv = *reinterpret_cast<const float2*>(Bv + c);
#pragma unroll
        for (int mt = 0; mt < 4; mt++) {
            const int r = row0 + mt * 16 + (lane >> 2);
            float2 v0, v1;
            v0.x = acc[mt][nt][0] + bv.x;
            v0.y = acc[mt][nt][1] + bv.y;
            v1.x = acc[mt][nt][2] + bv.x;
            v1.y = acc[mt][nt][3] + bv.y;
            *reinterpret_cast<float2*>(Y + (size_t)r * ND + c) = v0;
            *reinterpret_cast<float2*>(Y + (size_t)(r + 8) * ND + c) = v1;
        }
    }
}

extern "C" void kernel_launch(void* const* d_in, const int* in_sizes, int n_in,
                              void* d_out, int out_size) {
    const float* x = nullptr;
    const float* w = nullptr;
    const float* b = nullptr;
    for (int i = 0; i < n_in; i++) {
        if (in_sizes[i] == BATCH * KD)   x = (const float*)d_in[i];
        else if (in_sizes[i] == ND * KD) w = (const float*)d_in[i];
        else if (in_sizes[i] == ND)      b = (const float*)d_in[i];
    }
    float* out = (float*)d_out;

    cvt_w_kernel<<<(ND * KD / 4) / 256, 256>>>(w);   // ~1 us

    cudaFuncSetAttribute(gemm_fused_kernel,
                         cudaFuncAttributeMaxDynamicSharedMemorySize, SMEM_TOTAL);
    gemm_fused_kernel<<<(BATCH / BM) * (ND / BN), 128, SMEM_TOTAL>>>(x, b, out);
}